// round 3
// baseline (speedup 1.0000x reference)
#include <cuda_runtime.h>
#include <cuda_bf16.h>

// Problem constants
#define BB   8
#define SS   1024
#define DD   768
#define HH   16
#define PDIM 48
#define MTOT (BB * SS)   // 8192

// Scratch (device globals: allocation-free, allowed by harness rules)
__device__ float g_q[BB * HH * SS * PDIM];     // [b,h,s,pd]
__device__ float g_k[BB * HH * SS * PDIM];
__device__ float g_v[BB * HH * SS * PDIM];
__device__ float g_attn[BB * SS * DD];         // [b,s,d]

// ---------------------------------------------------------------------------
// GEMM: out[M,N] = A[M,K] @ W[K,N] + bias, M=8192, N=768, K=768
// BM=128, BN=128, BK=16, 256 threads, 8x8 micro-tile per thread
// (register tile split {ty*4, ty*4+64} x {tx*4, tx*4+64} -> conflict-free
//  LDS.128 phases).
// MODE 0: plain row-major out. MODE 1: scatter to [b,h,s,pd] head layout.
// ---------------------------------------------------------------------------
template <int MODE>
__global__ __launch_bounds__(256) void gemm768(const float* __restrict__ A,
                                               const float* __restrict__ W,
                                               const float* __restrict__ bias,
                                               float* __restrict__ out) {
    __shared__ float As[16][128];   // transposed: As[k][m]
    __shared__ float Bs[16][128];

    const int tid = threadIdx.x;
    const int m0 = blockIdx.y * 128;
    const int n0 = blockIdx.x * 128;
    const int ty = (tid >> 4) * 4;      // row base 0..60
    const int tx = (tid & 15) * 4;      // col base 0..60

    // A load: 128 rows x 16 k / 256 thr = 8 floats = 2x float4
    const int la_m = tid >> 2;          // 0..63 (second row at +64)
    const int la_k = (tid & 3) * 4;     // 0,4,8,12
    // B load: 16 rows x 128 cols / 256 thr = 8 floats = 2x float4
    const int lb_r = tid >> 4;          // 0..15
    const int lb_c = (tid & 15) * 4;    // 0..60 (second at +64)

    float acc[8][8];
#pragma unroll
    for (int i = 0; i < 8; i++)
#pragma unroll
        for (int j = 0; j < 8; j++) acc[i][j] = 0.0f;

    for (int k0 = 0; k0 < DD; k0 += 16) {
        float4 a0 = *(const float4*)&A[(size_t)(m0 + la_m) * DD + k0 + la_k];
        float4 a1 = *(const float4*)&A[(size_t)(m0 + la_m + 64) * DD + k0 + la_k];
        float4 b0 = *(const float4*)&W[(size_t)(k0 + lb_r) * DD + n0 + lb_c];
        float4 b1 = *(const float4*)&W[(size_t)(k0 + lb_r) * DD + n0 + lb_c + 64];
        __syncthreads();
        As[la_k + 0][la_m] = a0.x;
        As[la_k + 1][la_m] = a0.y;
        As[la_k + 2][la_m] = a0.z;
        As[la_k + 3][la_m] = a0.w;
        As[la_k + 0][la_m + 64] = a1.x;
        As[la_k + 1][la_m + 64] = a1.y;
        As[la_k + 2][la_m + 64] = a1.z;
        As[la_k + 3][la_m + 64] = a1.w;
        *(float4*)&Bs[lb_r][lb_c] = b0;
        *(float4*)&Bs[lb_r][lb_c + 64] = b1;
        __syncthreads();
#pragma unroll
        for (int k = 0; k < 16; k++) {
            float4 av0 = *(const float4*)&As[k][ty];
            float4 av1 = *(const float4*)&As[k][ty + 64];
            float4 bv0 = *(const float4*)&Bs[k][tx];
            float4 bv1 = *(const float4*)&Bs[k][tx + 64];
            float a[8] = {av0.x, av0.y, av0.z, av0.w, av1.x, av1.y, av1.z, av1.w};
            float b[8] = {bv0.x, bv0.y, bv0.z, bv0.w, bv1.x, bv1.y, bv1.z, bv1.w};
#pragma unroll
            for (int i = 0; i < 8; i++)
#pragma unroll
                for (int j = 0; j < 8; j++) acc[i][j] += a[i] * b[j];
        }
    }

#pragma unroll
    for (int i = 0; i < 8; i++) {
        const int m = m0 + ty + (i < 4 ? i : 60 + i);       // ty+i or ty+64+(i-4)
#pragma unroll
        for (int j = 0; j < 8; j++) {
            const int n = n0 + tx + (j < 4 ? j : 60 + j);
            const float v = acc[i][j] + bias[n];
            if (MODE == 0) {
                out[(size_t)m * DD + n] = v;
            } else {
                const int b = m >> 10;         // / SS
                const int s = m & 1023;
                const int h = n / PDIM;
                const int pd = n - h * PDIM;
                out[(((size_t)(b * HH + h) << 10) + s) * PDIM + pd] = v;
            }
        }
    }
}

// ---------------------------------------------------------------------------
// Flash attention (fp32): per CTA one (b,h) x 64-query tile; stream 64-key
// tiles with online softmax. 256 threads: ty=tid/16 owns rows ty*4..+3,
// tx=tid%16 owns interleaved cols c = tx+16j (scores) / dims d = tx+16dd (O).
// ---------------------------------------------------------------------------
#define QSTR 52
#define PSTR 68
#define ATTN_SMEM_FLOATS (3 * 64 * QSTR + 64 * PSTR)   // 14336
#define ATTN_SMEM_BYTES  (ATTN_SMEM_FLOATS * 4)        // 57344

__global__ __launch_bounds__(256) void attn_kernel(const float* __restrict__ Q,
                                                   const float* __restrict__ K,
                                                   const float* __restrict__ V,
                                                   float* __restrict__ out) {
    extern __shared__ float smem[];
    float* Qs = smem;                    // [64][52]
    float* Ks = smem + 64 * QSTR;        // [64][52]
    float* Vs = smem + 2 * 64 * QSTR;    // [64][52]
    float* Ps = smem + 3 * 64 * QSTR;    // [64][68]

    const int bh = blockIdx.y;           // b*16 + h
    const int q0 = blockIdx.x * 64;
    const float* Qb = Q + (size_t)bh * SS * PDIM;
    const float* Kb = K + (size_t)bh * SS * PDIM;
    const float* Vb = V + (size_t)bh * SS * PDIM;

    const int tid = threadIdx.x;
    const int ty = tid >> 4;   // 0..15
    const int tx = tid & 15;   // 0..15
    const float scale = 0.14433756729740643f;  // 1/sqrt(48)

    // Load Q tile (64 x 48) once
    for (int i = tid; i < 64 * 12; i += 256) {
        const int r = i / 12;
        const int c4 = (i - r * 12) * 4;
        *(float4*)&Qs[r * QSTR + c4] = *(const float4*)&Qb[(size_t)(q0 + r) * PDIM + c4];
    }

    float m_r[4], l_r[4], O[4][3];
#pragma unroll
    for (int i = 0; i < 4; i++) {
        m_r[i] = -1e30f;
        l_r[i] = 0.0f;
        O[i][0] = O[i][1] = O[i][2] = 0.0f;
    }

    for (int kt = 0; kt < 16; kt++) {
        const int k0 = kt * 64;
        __syncthreads();   // protect Ks/Vs (prev compute) and Ps (prev PV read)
        for (int i = tid; i < 64 * 12; i += 256) {
            const int r = i / 12;
            const int c4 = (i - r * 12) * 4;
            *(float4*)&Ks[r * QSTR + c4] = *(const float4*)&Kb[(size_t)(k0 + r) * PDIM + c4];
            *(float4*)&Vs[r * QSTR + c4] = *(const float4*)&Vb[(size_t)(k0 + r) * PDIM + c4];
        }
        __syncthreads();

        // --- scores: rows ty*4+i, cols tx+16j ---
        float sc[4][4];
#pragma unroll
        for (int i = 0; i < 4; i++)
#pragma unroll
            for (int j = 0; j < 4; j++) sc[i][j] = 0.0f;

#pragma unroll
        for (int kk = 0; kk < 48; kk += 4) {
            float4 qv[4];
#pragma unroll
            for (int i = 0; i < 4; i++)
                qv[i] = *(const float4*)&Qs[(ty * 4 + i) * QSTR + kk];
#pragma unroll
            for (int j = 0; j < 4; j++) {
                const float4 kv = *(const float4*)&Ks[(tx + 16 * j) * QSTR + kk];
#pragma unroll
                for (int i = 0; i < 4; i++) {
                    sc[i][j] += qv[i].x * kv.x + qv[i].y * kv.y +
                                qv[i].z * kv.z + qv[i].w * kv.w;
                }
            }
        }

        // --- online softmax per row (reduce over 16 lanes sharing ty) ---
        float alpha[4];
#pragma unroll
        for (int i = 0; i < 4; i++) {
            float mt = fmaxf(fmaxf(sc[i][0], sc[i][1]), fmaxf(sc[i][2], sc[i][3])) * scale;
#pragma unroll
            for (int d = 1; d < 16; d <<= 1)
                mt = fmaxf(mt, __shfl_xor_sync(0xffffffffu, mt, d));
            const float mnew = fmaxf(m_r[i], mt);
            float lt = 0.0f;
#pragma unroll
            for (int j = 0; j < 4; j++) {
                const float p = __expf(sc[i][j] * scale - mnew);
                sc[i][j] = p;
                lt += p;
            }
#pragma unroll
            for (int d = 1; d < 16; d <<= 1)
                lt += __shfl_xor_sync(0xffffffffu, lt, d);
            alpha[i] = __expf(m_r[i] - mnew);
            l_r[i] = alpha[i] * l_r[i] + lt;
            m_r[i] = mnew;
#pragma unroll
            for (int j = 0; j < 4; j++)
                Ps[(ty * 4 + i) * PSTR + tx + 16 * j] = sc[i][j];
        }
        __syncthreads();

        // --- O = alpha*O + P @ V : rows ty*4+i, dims tx+16dd ---
#pragma unroll
        for (int i = 0; i < 4; i++) {
            O[i][0] *= alpha[i];
            O[i][1] *= alpha[i];
            O[i][2] *= alpha[i];
        }
        for (int c4 = 0; c4 < 64; c4 += 4) {
            float4 pv[4];
#pragma unroll
            for (int i = 0; i < 4; i++)
                pv[i] = *(const float4*)&Ps[(ty * 4 + i) * PSTR + c4];
            const float* pf0 = (const float*)&pv[0];
            const float* pf1 = (const float*)&pv[1];
            const float* pf2 = (const float*)&pv[2];
            const float* pf3 = (const float*)&pv[3];
#pragma unroll
            for (int j = 0; j < 4; j++) {
                const int c = c4 + j;
                const float v0 = Vs[c * QSTR + tx];
                const float v1 = Vs[c * QSTR + tx + 16];
                const float v2 = Vs[c * QSTR + tx + 32];
                O[0][0] += pf0[j] * v0; O[0][1] += pf0[j] * v1; O[0][2] += pf0[j] * v2;
                O[1][0] += pf1[j] * v0; O[1][1] += pf1[j] * v1; O[1][2] += pf1[j] * v2;
                O[2][0] += pf2[j] * v0; O[2][1] += pf2[j] * v1; O[2][2] += pf2[j] * v2;
                O[3][0] += pf3[j] * v0; O[3][1] += pf3[j] * v1; O[3][2] += pf3[j] * v2;
            }
        }
    }

    // epilogue: normalize and write to [b,s,d] concat layout
    const int b = bh >> 4;
    const int h = bh & 15;
#pragma unroll
    for (int i = 0; i < 4; i++) {
        const int srow = q0 + ty * 4 + i;
        const float inv = 1.0f / l_r[i];
        float* orow = g_attn + ((size_t)(b * SS + srow)) * DD + h * PDIM;
        orow[tx]      = O[i][0] * inv;
        orow[tx + 16] = O[i][1] * inv;
        orow[tx + 32] = O[i][2] * inv;
    }
}

// ---------------------------------------------------------------------------
extern "C" void kernel_launch(void* const* d_in, const int* in_sizes, int n_in,
                              void* d_out, int out_size) {
    const float* X  = (const float*)d_in[0];
    const float* Wq = (const float*)d_in[1];
    const float* bq = (const float*)d_in[2];
    const float* Wk = (const float*)d_in[3];
    const float* bk = (const float*)d_in[4];
    const float* Wv = (const float*)d_in[5];
    const float* bv = (const float*)d_in[6];
    const float* Wo = (const float*)d_in[7];
    const float* bo = (const float*)d_in[8];
    float* out = (float*)d_out;

    float *qp, *kp, *vp, *ap;
    cudaGetSymbolAddress((void**)&qp, g_q);
    cudaGetSymbolAddress((void**)&kp, g_k);
    cudaGetSymbolAddress((void**)&vp, g_v);
    cudaGetSymbolAddress((void**)&ap, g_attn);

    cudaFuncSetAttribute(attn_kernel, cudaFuncAttributeMaxDynamicSharedMemorySize,
                         ATTN_SMEM_BYTES);

    dim3 gg(DD / 128, MTOT / 128);   // (6, 64)
    gemm768<1><<<gg, 256>>>(X, Wq, bq, qp);
    gemm768<1><<<gg, 256>>>(X, Wk, bk, kp);
    gemm768<1><<<gg, 256>>>(X, Wv, bv, vp);

    attn_kernel<<<dim3(SS / 64, BB * HH), 256, ATTN_SMEM_BYTES>>>(qp, kp, vp, ap);

    gemm768<0><<<gg, 256>>>(ap, Wo, bo, out);
}

// round 5
// speedup vs baseline: 1.2711x; 1.2711x over previous
#include <cuda_runtime.h>
#include <cuda_bf16.h>

// Problem constants
#define BB   8
#define SS   1024
#define DD   768
#define HH   16
#define PDIM 48
#define MTOT (BB * SS)   // 8192
#define WSZ  (DD * DD)   // 589824

// ---------------------------------------------------------------------------
// Scratch (device globals: allocation-free)
// ---------------------------------------------------------------------------
__device__ __nv_bfloat16 g_xhi[MTOT * DD], g_xlo[MTOT * DD];   // split(inputs)
__device__ __nv_bfloat16 g_chi[MTOT * DD], g_clo[MTOT * DD];   // split(attn out)
__device__ __nv_bfloat16 g_wthi[4 * WSZ], g_wtlo[4 * WSZ];     // Wt[n][k] split, slots q,k,v,o
__device__ float g_q[BB * HH * SS * PDIM];   // [b,h,s,pd]
__device__ float g_k[BB * HH * SS * PDIM];   // [b,h,s,pd]
__device__ float g_v[BB * HH * SS * PDIM];   // [b,h,pd,s]  (pd-major!)
__device__ float g_attn[MTOT * DD];          // [b,s,d]

// ---------------------------------------------------------------------------
// split fp32 -> (hi, lo) bf16, 4 elems/thread
// ---------------------------------------------------------------------------
__global__ void splitk(const float* __restrict__ x, __nv_bfloat16* __restrict__ hi,
                       __nv_bfloat16* __restrict__ lo, int n4) {
    int i = blockIdx.x * 256 + threadIdx.x;
    if (i >= n4) return;
    float4 v = ((const float4*)x)[i];
    __nv_bfloat16 h0 = __float2bfloat16(v.x), h1 = __float2bfloat16(v.y);
    __nv_bfloat16 h2 = __float2bfloat16(v.z), h3 = __float2bfloat16(v.w);
    __nv_bfloat16 l0 = __float2bfloat16(v.x - __bfloat162float(h0));
    __nv_bfloat16 l1 = __float2bfloat16(v.y - __bfloat162float(h1));
    __nv_bfloat16 l2 = __float2bfloat16(v.z - __bfloat162float(h2));
    __nv_bfloat16 l3 = __float2bfloat16(v.w - __bfloat162float(h3));
    __nv_bfloat162* ph = (__nv_bfloat162*)&hi[4 * i];
    __nv_bfloat162* pl = (__nv_bfloat162*)&lo[4 * i];
    ph[0] = __nv_bfloat162(h0, h1); ph[1] = __nv_bfloat162(h2, h3);
    pl[0] = __nv_bfloat162(l0, l1); pl[1] = __nv_bfloat162(l2, l3);
}

// ---------------------------------------------------------------------------
// Weight transpose + split: Wt[n][k] = W[k][n]; 32x32 tiles, 4 weights by z.
// ---------------------------------------------------------------------------
__global__ void wsplit(const float* __restrict__ w0, const float* __restrict__ w1,
                       const float* __restrict__ w2, const float* __restrict__ w3,
                       __nv_bfloat16* __restrict__ whi, __nv_bfloat16* __restrict__ wlo) {
    __shared__ float tile[32][33];
    const int z = blockIdx.z;
    const float* W = (z == 0) ? w0 : (z == 1) ? w1 : (z == 2) ? w2 : w3;
    const int x0 = blockIdx.x * 32;   // n
    const int y0 = blockIdx.y * 32;   // k
    const int tx = threadIdx.x, ty = threadIdx.y;
    for (int j = ty; j < 32; j += 8)
        tile[j][tx] = W[(size_t)(y0 + j) * DD + x0 + tx];
    __syncthreads();
    for (int j = ty; j < 32; j += 8) {
        float v = tile[tx][j];                 // W[y0+tx][x0+j]
        __nv_bfloat16 h = __float2bfloat16(v);
        __nv_bfloat16 l = __float2bfloat16(v - __bfloat162float(h));
        size_t idx = (size_t)z * WSZ + (size_t)(x0 + j) * DD + y0 + tx;
        whi[idx] = h;
        wlo[idx] = l;
    }
}

// ---------------------------------------------------------------------------
// bf16-split tensor-core GEMM: out[M,N] = A @ W (+bias), K=768.
// CTA 128x64, BK=32, 256 thr (8 warps 4x2), warp 32x32, mma m16n8k16.
// MODE 0: plain row-major fp32 out (weight preselected).
// MODE 1: fused QKV (blockIdx.x/12 = weight; scatter q/k s-major, v pd-major).
// ---------------------------------------------------------------------------
__device__ __forceinline__ void mma16816(float* c, const unsigned* a, const unsigned* b) {
    asm volatile(
        "mma.sync.aligned.m16n8k16.row.col.f32.bf16.bf16.f32 "
        "{%0,%1,%2,%3},{%4,%5,%6,%7},{%8,%9},{%0,%1,%2,%3};"
        : "+f"(c[0]), "+f"(c[1]), "+f"(c[2]), "+f"(c[3])
        : "r"(a[0]), "r"(a[1]), "r"(a[2]), "r"(a[3]), "r"(b[0]), "r"(b[1]));
}

template <int MODE>
__global__ __launch_bounds__(256) void mma_gemm(
    const __nv_bfloat16* __restrict__ ahi, const __nv_bfloat16* __restrict__ alo,
    const __nv_bfloat16* __restrict__ wthi, const __nv_bfloat16* __restrict__ wtlo,
    const float* __restrict__ bias0, const float* __restrict__ bias1,
    const float* __restrict__ bias2,
    float* __restrict__ d0, float* __restrict__ d1, float* __restrict__ d2) {
    __shared__ __nv_bfloat16 Ah[128 * 40], Al[128 * 40];
    __shared__ __nv_bfloat16 Bh[64 * 40], Bl[64 * 40];

    const int tid = threadIdx.x;
    const int lane = tid & 31, wid = tid >> 5;
    const int wm = wid & 3, wn = wid >> 2;
    const int g = lane >> 2, tg = lane & 3;
    const int m0 = blockIdx.y * 128;

    int w, nloc;
    if (MODE == 1) { w = blockIdx.x / 12; nloc = (blockIdx.x % 12) * 64; }
    else           { w = 0;               nloc = blockIdx.x * 64; }
    const __nv_bfloat16* Wh = wthi + (size_t)w * WSZ;
    const __nv_bfloat16* Wl = wtlo + (size_t)w * WSZ;
    const float* bias = (MODE == 1) ? (w == 0 ? bias0 : (w == 1 ? bias1 : bias2)) : bias0;

    // gmem load coords
    const int ar = tid >> 1, ac = (tid & 1) * 16;     // A: 128 rows x 32 k
    const int br = tid >> 2, bc = (tid & 3) * 8;      // B: 64 rows(n) x 32 k

    float acc[2][4][4];
#pragma unroll
    for (int mt = 0; mt < 2; mt++)
#pragma unroll
        for (int nt = 0; nt < 4; nt++)
#pragma unroll
            for (int e = 0; e < 4; e++) acc[mt][nt][e] = 0.0f;

    for (int k0 = 0; k0 < DD; k0 += 32) {
        const size_t aoff = (size_t)(m0 + ar) * DD + k0 + ac;
        const size_t boff = (size_t)(nloc + br) * DD + k0 + bc;
        uint4 vah0 = *(const uint4*)&ahi[aoff];
        uint4 vah1 = *(const uint4*)&ahi[aoff + 8];
        uint4 val0 = *(const uint4*)&alo[aoff];
        uint4 val1 = *(const uint4*)&alo[aoff + 8];
        uint4 vbh  = *(const uint4*)&Wh[boff];
        uint4 vbl  = *(const uint4*)&Wl[boff];
        __syncthreads();
        {
            uint2* s = (uint2*)&Ah[ar * 40 + ac];
            s[0] = make_uint2(vah0.x, vah0.y); s[1] = make_uint2(vah0.z, vah0.w);
            s[2] = make_uint2(vah1.x, vah1.y); s[3] = make_uint2(vah1.z, vah1.w);
            uint2* t = (uint2*)&Al[ar * 40 + ac];
            t[0] = make_uint2(val0.x, val0.y); t[1] = make_uint2(val0.z, val0.w);
            t[2] = make_uint2(val1.x, val1.y); t[3] = make_uint2(val1.z, val1.w);
            uint2* u = (uint2*)&Bh[br * 40 + bc];
            u[0] = make_uint2(vbh.x, vbh.y);   u[1] = make_uint2(vbh.z, vbh.w);
            uint2* v = (uint2*)&Bl[br * 40 + bc];
            v[0] = make_uint2(vbl.x, vbl.y);   v[1] = make_uint2(vbl.z, vbl.w);
        }
        __syncthreads();

#pragma unroll
        for (int kh = 0; kh < 32; kh += 16) {
            unsigned a_h[2][4], a_l[2][4], b_h[4][2], b_l[4][2];
#pragma unroll
            for (int mt = 0; mt < 2; mt++) {
                const int rb = wm * 32 + mt * 16 + g;
                a_h[mt][0] = *(const unsigned*)&Ah[(rb)     * 40 + kh + 2 * tg];
                a_h[mt][1] = *(const unsigned*)&Ah[(rb + 8) * 40 + kh + 2 * tg];
                a_h[mt][2] = *(const unsigned*)&Ah[(rb)     * 40 + kh + 2 * tg + 8];
                a_h[mt][3] = *(const unsigned*)&Ah[(rb + 8) * 40 + kh + 2 * tg + 8];
                a_l[mt][0] = *(const unsigned*)&Al[(rb)     * 40 + kh + 2 * tg];
                a_l[mt][1] = *(const unsigned*)&Al[(rb + 8) * 40 + kh + 2 * tg];
                a_l[mt][2] = *(const unsigned*)&Al[(rb)     * 40 + kh + 2 * tg + 8];
                a_l[mt][3] = *(const unsigned*)&Al[(rb + 8) * 40 + kh + 2 * tg + 8];
            }
#pragma unroll
            for (int nt = 0; nt < 4; nt++) {
                const int nb = wn * 32 + nt * 8 + g;
                b_h[nt][0] = *(const unsigned*)&Bh[nb * 40 + kh + 2 * tg];
                b_h[nt][1] = *(const unsigned*)&Bh[nb * 40 + kh + 2 * tg + 8];
                b_l[nt][0] = *(const unsigned*)&Bl[nb * 40 + kh + 2 * tg];
                b_l[nt][1] = *(const unsigned*)&Bl[nb * 40 + kh + 2 * tg + 8];
            }
#pragma unroll
            for (int mt = 0; mt < 2; mt++)
#pragma unroll
                for (int nt = 0; nt < 4; nt++) {
                    mma16816(acc[mt][nt], a_h[mt], b_h[nt]);
                    mma16816(acc[mt][nt], a_h[mt], b_l[nt]);
                    mma16816(acc[mt][nt], a_l[mt], b_h[nt]);
                }
        }
    }

    // epilogue
#pragma unroll
    for (int mt = 0; mt < 2; mt++) {
        const int mA = m0 + wm * 32 + mt * 16 + g;
#pragma unroll
        for (int nt = 0; nt < 4; nt++) {
            const int n = nloc + wn * 32 + nt * 8 + tg * 2;
            const float b0v = bias[n], b1v = bias[n + 1];
            const float v00 = acc[mt][nt][0] + b0v;
            const float v01 = acc[mt][nt][1] + b1v;
            const float v10 = acc[mt][nt][2] + b0v;
            const float v11 = acc[mt][nt][3] + b1v;
            if (MODE == 0) {
                *(float2*)&d0[(size_t)mA * DD + n] = make_float2(v00, v01);
                *(float2*)&d0[(size_t)(mA + 8) * DD + n] = make_float2(v10, v11);
            } else {
                const int h = n / PDIM, pd = n - h * PDIM;   // pd even, pd+1 same head
                if (w < 2) {
                    float* dst = (w == 0) ? d0 : d1;         // [b,h,s,pd]
                    const int b_ = mA >> 10, s0 = mA & 1023;
                    size_t i0 = (((size_t)(b_ * HH + h) << 10) + s0) * PDIM + pd;
                    *(float2*)&dst[i0] = make_float2(v00, v01);
                    *(float2*)&dst[i0 + 8 * PDIM] = make_float2(v10, v11);
                } else {                                      // V: [b,h,pd,s]
                    const int b_ = mA >> 10, s0 = mA & 1023;
                    size_t i0 = (((size_t)(b_ * HH + h) * PDIM + pd) << 10) + s0;
                    d2[i0] = v00;  d2[i0 + SS] = v01;
                    d2[i0 + 8] = v10; d2[i0 + SS + 8] = v11;
                }
            }
        }
    }
}

// ---------------------------------------------------------------------------
// Flash attention (fp32). Q/K [b,h,s,pd]; V [b,h,pd,s] (pd-major) so the PV
// loop is all-float4 from smem Vt[48][68]. Scale folded into Q load.
// ---------------------------------------------------------------------------
#define QSTR 52
#define VSTR 68
#define PSTR 68
#define OFF_K  (64 * QSTR)
#define OFF_VT (2 * 64 * QSTR)
#define OFF_P  (OFF_VT + PDIM * VSTR)
#define ATTN_SMEM_FLOATS (OFF_P + 64 * PSTR)
#define ATTN_SMEM_BYTES  (ATTN_SMEM_FLOATS * 4)

__global__ __launch_bounds__(256) void attn_kernel(const float* __restrict__ Q,
                                                   const float* __restrict__ K,
                                                   const float* __restrict__ V,
                                                   float* __restrict__ out) {
    extern __shared__ float smem[];
    float* Qs  = smem;                 // [64][52]
    float* Ks  = smem + OFF_K;         // [64][52]
    float* Vts = smem + OFF_VT;        // [48][68]  Vt[pd][s]
    float* Ps  = smem + OFF_P;         // [64][68]

    const int bh = blockIdx.y;
    const int q0 = blockIdx.x * 64;
    const float* Qb = Q + (size_t)bh * SS * PDIM;
    const float* Kb = K + (size_t)bh * SS * PDIM;
    const float* Vb = V + (size_t)bh * SS * PDIM;   // pd-major: Vb[pd*SS + s]

    const int tid = threadIdx.x;
    const int ty = tid >> 4;
    const int tx = tid & 15;
    const float scale = 0.14433756729740643f;  // 1/sqrt(48)

    // Load Q tile scaled
    for (int i = tid; i < 64 * 12; i += 256) {
        const int r = i / 12;
        const int c4 = (i - r * 12) * 4;
        float4 qv = *(const float4*)&Qb[(size_t)(q0 + r) * PDIM + c4];
        qv.x *= scale; qv.y *= scale; qv.z *= scale; qv.w *= scale;
        *(float4*)&Qs[r * QSTR + c4] = qv;
    }

    float m_r[4], l_r[4], O[4][3];
#pragma unroll
    for (int i = 0; i < 4; i++) {
        m_r[i] = -1e30f; l_r[i] = 0.0f;
        O[i][0] = O[i][1] = O[i][2] = 0.0f;
    }

    for (int kt = 0; kt < 16; kt++) {
        const int k0 = kt * 64;
        __syncthreads();
        for (int i = tid; i < 64 * 12; i += 256) {
            const int r = i / 12;
            const int c4 = (i - r * 12) * 4;
            *(float4*)&Ks[r * QSTR + c4] = *(const float4*)&Kb[(size_t)(k0 + r) * PDIM + c4];
        }
        for (int i = tid; i < PDIM * 16; i += 256) {   // 48 rows x 16 float4
            const int r = i >> 4;
            const int c4 = (i & 15) * 4;
            *(float4*)&Vts[r * VSTR + c4] = *(const float4*)&Vb[(size_t)r * SS + k0 + c4];
        }
        __syncthreads();

        // scores
        float sc[4][4];
#pragma unroll
        for (int i = 0; i < 4; i++)
#pragma unroll
            for (int j = 0; j < 4; j++) sc[i][j] = 0.0f;
#pragma unroll
        for (int kk = 0; kk < 48; kk += 4) {
            float4 qv[4];
#pragma unroll
            for (int i = 0; i < 4; i++)
                qv[i] = *(const float4*)&Qs[(ty * 4 + i) * QSTR + kk];
#pragma unroll
            for (int j = 0; j < 4; j++) {
                const float4 kv = *(const float4*)&Ks[(tx + 16 * j) * QSTR + kk];
#pragma unroll
                for (int i = 0; i < 4; i++)
                    sc[i][j] += qv[i].x * kv.x + qv[i].y * kv.y +
                                qv[i].z * kv.z + qv[i].w * kv.w;
            }
        }

        // online softmax (scores pre-scaled)
        float alpha[4];
#pragma unroll
        for (int i = 0; i < 4; i++) {
            float mt = fmaxf(fmaxf(sc[i][0], sc[i][1]), fmaxf(sc[i][2], sc[i][3]));
#pragma unroll
            for (int d = 1; d < 16; d <<= 1)
                mt = fmaxf(mt, __shfl_xor_sync(0xffffffffu, mt, d));
            const float mnew = fmaxf(m_r[i], mt);
            float lt = 0.0f;
#pragma unroll
            for (int j = 0; j < 4; j++) {
                const float p = __expf(sc[i][j] - mnew);
                sc[i][j] = p;
                lt += p;
            }
#pragma unroll
            for (int d = 1; d < 16; d <<= 1)
                lt += __shfl_xor_sync(0xffffffffu, lt, d);
            alpha[i] = __expf(m_r[i] - mnew);
            l_r[i] = alpha[i] * l_r[i] + lt;
            m_r[i] = mnew;
#pragma unroll
            for (int j = 0; j < 4; j++)
                Ps[(ty * 4 + i) * PSTR + tx + 16 * j] = sc[i][j];
        }
        __syncthreads();

        // O = alpha*O + P @ V (all float4)
#pragma unroll
        for (int i = 0; i < 4; i++) {
            O[i][0] *= alpha[i]; O[i][1] *= alpha[i]; O[i][2] *= alpha[i];
        }
        for (int c4 = 0; c4 < 64; c4 += 4) {
            const float4 v0 = *(const float4*)&Vts[(tx)      * VSTR + c4];
            const float4 v1 = *(const float4*)&Vts[(tx + 16) * VSTR + c4];
            const float4 v2 = *(const float4*)&Vts[(tx + 32) * VSTR + c4];
#pragma unroll
            for (int i = 0; i < 4; i++) {
                const float4 p = *(const float4*)&Ps[(ty * 4 + i) * PSTR + c4];
                O[i][0] += p.x * v0.x + p.y * v0.y + p.z * v0.z + p.w * v0.w;
                O[i][1] += p.x * v1.x + p.y * v1.y + p.z * v1.z + p.w * v1.w;
                O[i][2] += p.x * v2.x + p.y * v2.y + p.z * v2.z + p.w * v2.w;
            }
        }
    }

    const int b = bh >> 4;
    const int h = bh & 15;
#pragma unroll
    for (int i = 0; i < 4; i++) {
        const int srow = q0 + ty * 4 + i;
        const float inv = 1.0f / l_r[i];
        float* orow = out + ((size_t)(b * SS + srow)) * DD + h * PDIM;
        orow[tx]      = O[i][0] * inv;
        orow[tx + 16] = O[i][1] * inv;
        orow[tx + 32] = O[i][2] * inv;
    }
}

// ---------------------------------------------------------------------------
extern "C" void kernel_launch(void* const* d_in, const int* in_sizes, int n_in,
                              void* d_out, int out_size) {
    const float* X  = (const float*)d_in[0];
    const float* Wq = (const float*)d_in[1];
    const float* bq = (const float*)d_in[2];
    const float* Wk = (const float*)d_in[3];
    const float* bk = (const float*)d_in[4];
    const float* Wv = (const float*)d_in[5];
    const float* bv = (const float*)d_in[6];
    const float* Wo = (const float*)d_in[7];
    const float* bo = (const float*)d_in[8];
    float* out = (float*)d_out;

    __nv_bfloat16 *xhi, *xlo, *chi, *clo, *wthi, *wtlo;
    float *qp, *kp, *vp, *ap;
    cudaGetSymbolAddress((void**)&xhi, g_xhi);
    cudaGetSymbolAddress((void**)&xlo, g_xlo);
    cudaGetSymbolAddress((void**)&chi, g_chi);
    cudaGetSymbolAddress((void**)&clo, g_clo);
    cudaGetSymbolAddress((void**)&wthi, g_wthi);
    cudaGetSymbolAddress((void**)&wtlo, g_wtlo);
    cudaGetSymbolAddress((void**)&qp, g_q);
    cudaGetSymbolAddress((void**)&kp, g_k);
    cudaGetSymbolAddress((void**)&vp, g_v);
    cudaGetSymbolAddress((void**)&ap, g_attn);

    cudaFuncSetAttribute(attn_kernel, cudaFuncAttributeMaxDynamicSharedMemorySize,
                         ATTN_SMEM_BYTES);

    const int n4 = MTOT * DD / 4;
    splitk<<<(n4 + 255) / 256, 256>>>(X, xhi, xlo, n4);
    wsplit<<<dim3(24, 24, 4), dim3(32, 8)>>>(Wq, Wk, Wv, Wo, wthi, wtlo);

    // fused QKV
    mma_gemm<1><<<dim3(36, 64), 256>>>(xhi, xlo, wthi, wtlo, bq, bk, bv, qp, kp, vp);

    attn_kernel<<<dim3(SS / 64, BB * HH), 256, ATTN_SMEM_BYTES>>>(qp, kp, vp, ap);

    splitk<<<(n4 + 255) / 256, 256>>>(ap, chi, clo, n4);
    mma_gemm<0><<<dim3(12, 64), 256>>>(chi, clo, wthi + 3 * (size_t)WSZ,
                                       wtlo + 3 * (size_t)WSZ, bo, nullptr, nullptr,
                                       out, nullptr, nullptr);
}

// round 9
// speedup vs baseline: 1.5194x; 1.1954x over previous
#include <cuda_runtime.h>
#include <cuda_bf16.h>

// Problem constants
#define BB   8
#define SS   1024
#define DD   768
#define HH   16
#define PDIM 48
#define MTOT (BB * SS)   // 8192
#define WSZ  (DD * DD)   // 589824

// ---------------------------------------------------------------------------
// Scratch (device globals: allocation-free)
// ---------------------------------------------------------------------------
__device__ __nv_bfloat16 g_xhi[MTOT * DD], g_xlo[MTOT * DD];   // split(inputs)
__device__ __nv_bfloat16 g_chi[MTOT * DD], g_clo[MTOT * DD];   // split(attn out)
__device__ __nv_bfloat16 g_wthi[4 * WSZ], g_wtlo[4 * WSZ];     // Wt[n][k] split, slots q,k,v,o
__device__ float g_q[BB * HH * SS * PDIM];   // [b,h,s,pd]
__device__ float g_k[BB * HH * SS * PDIM];   // [b,h,s,pd]
__device__ float g_v[BB * HH * SS * PDIM];   // [b,h,pd,s]  (pd-major!)
__device__ float g_attn[MTOT * DD];          // [b,s,d]

// ---------------------------------------------------------------------------
// helpers
// ---------------------------------------------------------------------------
__device__ __forceinline__ void split2(float x, float y, unsigned& hi, unsigned& lo) {
    __nv_bfloat16 hx = __float2bfloat16(x), hy = __float2bfloat16(y);
    __nv_bfloat16 lx = __float2bfloat16(x - __bfloat162float(hx));
    __nv_bfloat16 ly = __float2bfloat16(y - __bfloat162float(hy));
    __nv_bfloat162 h2(hx, hy), l2(lx, ly);
    hi = *reinterpret_cast<unsigned*>(&h2);
    lo = *reinterpret_cast<unsigned*>(&l2);
}

__device__ __forceinline__ void mma16816(float* c, const unsigned* a, const unsigned* b) {
    asm volatile(
        "mma.sync.aligned.m16n8k16.row.col.f32.bf16.bf16.f32 "
        "{%0,%1,%2,%3},{%4,%5,%6,%7},{%8,%9},{%0,%1,%2,%3};"
        : "+f"(c[0]), "+f"(c[1]), "+f"(c[2]), "+f"(c[3])
        : "r"(a[0]), "r"(a[1]), "r"(a[2]), "r"(a[3]), "r"(b[0]), "r"(b[1]));
}

// ---------------------------------------------------------------------------
// split fp32 -> (hi, lo) bf16, 4 elems/thread
// ---------------------------------------------------------------------------
__global__ void splitk(const float* __restrict__ x, __nv_bfloat16* __restrict__ hi,
                       __nv_bfloat16* __restrict__ lo, int n4) {
    int i = blockIdx.x * 256 + threadIdx.x;
    if (i >= n4) return;
    float4 v = ((const float4*)x)[i];
    unsigned h0, l0, h1, l1;
    split2(v.x, v.y, h0, l0);
    split2(v.z, v.w, h1, l1);
    unsigned* ph = (unsigned*)&hi[4 * i];
    unsigned* pl = (unsigned*)&lo[4 * i];
    ph[0] = h0; ph[1] = h1;
    pl[0] = l0; pl[1] = l1;
}

// ---------------------------------------------------------------------------
// Weight transpose + split: Wt[n][k] = W[k][n]; 32x32 tiles, 4 weights by z.
// ---------------------------------------------------------------------------
__global__ void wsplit(const float* __restrict__ w0, const float* __restrict__ w1,
                       const float* __restrict__ w2, const float* __restrict__ w3,
                       __nv_bfloat16* __restrict__ whi, __nv_bfloat16* __restrict__ wlo) {
    __shared__ float tile[32][33];
    const int z = blockIdx.z;
    const float* W = (z == 0) ? w0 : (z == 1) ? w1 : (z == 2) ? w2 : w3;
    const int x0 = blockIdx.x * 32;   // n
    const int y0 = blockIdx.y * 32;   // k
    const int tx = threadIdx.x, ty = threadIdx.y;
    for (int j = ty; j < 32; j += 8)
        tile[j][tx] = W[(size_t)(y0 + j) * DD + x0 + tx];
    __syncthreads();
    for (int j = ty; j < 32; j += 8) {
        float v = tile[tx][j];                 // W[y0+tx][x0+j]
        __nv_bfloat16 h = __float2bfloat16(v);
        __nv_bfloat16 l = __float2bfloat16(v - __bfloat162float(h));
        size_t idx = (size_t)z * WSZ + (size_t)(x0 + j) * DD + y0 + tx;
        whi[idx] = h;
        wlo[idx] = l;
    }
}

// ---------------------------------------------------------------------------
// bf16-split tensor-core GEMM: out[M,N] = A @ W (+bias), K=768.
// CTA 128x64, BK=32, 256 thr (8 warps 4x2), warp 32x32, mma m16n8k16.
// MODE 0: plain row-major fp32 out. MODE 1: fused QKV scatter.
// ---------------------------------------------------------------------------
template <int MODE>
__global__ __launch_bounds__(256) void mma_gemm(
    const __nv_bfloat16* __restrict__ ahi, const __nv_bfloat16* __restrict__ alo,
    const __nv_bfloat16* __restrict__ wthi, const __nv_bfloat16* __restrict__ wtlo,
    const float* __restrict__ bias0, const float* __restrict__ bias1,
    const float* __restrict__ bias2,
    float* __restrict__ d0, float* __restrict__ d1, float* __restrict__ d2) {
    __shared__ __nv_bfloat16 Ah[128 * 40], Al[128 * 40];
    __shared__ __nv_bfloat16 Bh[64 * 40], Bl[64 * 40];

    const int tid = threadIdx.x;
    const int lane = tid & 31, wid = tid >> 5;
    const int wm = wid & 3, wn = wid >> 2;
    const int g = lane >> 2, tg = lane & 3;
    const int m0 = blockIdx.y * 128;

    int w, nloc;
    if (MODE == 1) { w = blockIdx.x / 12; nloc = (blockIdx.x % 12) * 64; }
    else           { w = 0;               nloc = blockIdx.x * 64; }
    const __nv_bfloat16* Wh = wthi + (size_t)w * WSZ;
    const __nv_bfloat16* Wl = wtlo + (size_t)w * WSZ;
    const float* bias = (MODE == 1) ? (w == 0 ? bias0 : (w == 1 ? bias1 : bias2)) : bias0;

    const int ar = tid >> 1, ac = (tid & 1) * 16;     // A: 128 rows x 32 k
    const int br = tid >> 2, bc = (tid & 3) * 8;      // B: 64 rows(n) x 32 k

    float acc[2][4][4];
#pragma unroll
    for (int mt = 0; mt < 2; mt++)
#pragma unroll
        for (int nt = 0; nt < 4; nt++)
#pragma unroll
            for (int e = 0; e < 4; e++) acc[mt][nt][e] = 0.0f;

    for (int k0 = 0; k0 < DD; k0 += 32) {
        const size_t aoff = (size_t)(m0 + ar) * DD + k0 + ac;
        const size_t boff = (size_t)(nloc + br) * DD + k0 + bc;
        uint4 vah0 = *(const uint4*)&ahi[aoff];
        uint4 vah1 = *(const uint4*)&ahi[aoff + 8];
        uint4 val0 = *(const uint4*)&alo[aoff];
        uint4 val1 = *(const uint4*)&alo[aoff + 8];
        uint4 vbh  = *(const uint4*)&Wh[boff];
        uint4 vbl  = *(const uint4*)&Wl[boff];
        __syncthreads();
        {
            uint2* s = (uint2*)&Ah[ar * 40 + ac];
            s[0] = make_uint2(vah0.x, vah0.y); s[1] = make_uint2(vah0.z, vah0.w);
            s[2] = make_uint2(vah1.x, vah1.y); s[3] = make_uint2(vah1.z, vah1.w);
            uint2* t = (uint2*)&Al[ar * 40 + ac];
            t[0] = make_uint2(val0.x, val0.y); t[1] = make_uint2(val0.z, val0.w);
            t[2] = make_uint2(val1.x, val1.y); t[3] = make_uint2(val1.z, val1.w);
            uint2* u = (uint2*)&Bh[br * 40 + bc];
            u[0] = make_uint2(vbh.x, vbh.y);   u[1] = make_uint2(vbh.z, vbh.w);
            uint2* v = (uint2*)&Bl[br * 40 + bc];
            v[0] = make_uint2(vbl.x, vbl.y);   v[1] = make_uint2(vbl.z, vbl.w);
        }
        __syncthreads();

#pragma unroll
        for (int kh = 0; kh < 32; kh += 16) {
            unsigned a_h[2][4], a_l[2][4], b_h[4][2], b_l[4][2];
#pragma unroll
            for (int mt = 0; mt < 2; mt++) {
                const int rb = wm * 32 + mt * 16 + g;
                a_h[mt][0] = *(const unsigned*)&Ah[(rb)     * 40 + kh + 2 * tg];
                a_h[mt][1] = *(const unsigned*)&Ah[(rb + 8) * 40 + kh + 2 * tg];
                a_h[mt][2] = *(const unsigned*)&Ah[(rb)     * 40 + kh + 2 * tg + 8];
                a_h[mt][3] = *(const unsigned*)&Ah[(rb + 8) * 40 + kh + 2 * tg + 8];
                a_l[mt][0] = *(const unsigned*)&Al[(rb)     * 40 + kh + 2 * tg];
                a_l[mt][1] = *(const unsigned*)&Al[(rb + 8) * 40 + kh + 2 * tg];
                a_l[mt][2] = *(const unsigned*)&Al[(rb)     * 40 + kh + 2 * tg + 8];
                a_l[mt][3] = *(const unsigned*)&Al[(rb + 8) * 40 + kh + 2 * tg + 8];
            }
#pragma unroll
            for (int nt = 0; nt < 4; nt++) {
                const int nb = wn * 32 + nt * 8 + g;
                b_h[nt][0] = *(const unsigned*)&Bh[nb * 40 + kh + 2 * tg];
                b_h[nt][1] = *(const unsigned*)&Bh[nb * 40 + kh + 2 * tg + 8];
                b_l[nt][0] = *(const unsigned*)&Bl[nb * 40 + kh + 2 * tg];
                b_l[nt][1] = *(const unsigned*)&Bl[nb * 40 + kh + 2 * tg + 8];
            }
#pragma unroll
            for (int mt = 0; mt < 2; mt++)
#pragma unroll
                for (int nt = 0; nt < 4; nt++) {
                    mma16816(acc[mt][nt], a_h[mt], b_h[nt]);
                    mma16816(acc[mt][nt], a_h[mt], b_l[nt]);
                    mma16816(acc[mt][nt], a_l[mt], b_h[nt]);
                }
        }
    }

    // epilogue
#pragma unroll
    for (int mt = 0; mt < 2; mt++) {
        const int mA = m0 + wm * 32 + mt * 16 + g;
#pragma unroll
        for (int nt = 0; nt < 4; nt++) {
            const int n = nloc + wn * 32 + nt * 8 + tg * 2;
            const float b0v = bias[n], b1v = bias[n + 1];
            const float v00 = acc[mt][nt][0] + b0v;
            const float v01 = acc[mt][nt][1] + b1v;
            const float v10 = acc[mt][nt][2] + b0v;
            const float v11 = acc[mt][nt][3] + b1v;
            if (MODE == 0) {
                *(float2*)&d0[(size_t)mA * DD + n] = make_float2(v00, v01);
                *(float2*)&d0[(size_t)(mA + 8) * DD + n] = make_float2(v10, v11);
            } else {
                const int h = n / PDIM, pd = n - h * PDIM;   // pd even, pd+1 same head
                if (w < 2) {
                    float* dst = (w == 0) ? d0 : d1;         // [b,h,s,pd]
                    const int b_ = mA >> 10, s0 = mA & 1023;
                    size_t i0 = (((size_t)(b_ * HH + h) << 10) + s0) * PDIM + pd;
                    *(float2*)&dst[i0] = make_float2(v00, v01);
                    *(float2*)&dst[i0 + 8 * PDIM] = make_float2(v10, v11);
                } else {                                      // V: [b,h,pd,s]
                    const int b_ = mA >> 10, s0 = mA & 1023;
                    size_t i0 = (((size_t)(b_ * HH + h) * PDIM + pd) << 10) + s0;
                    d2[i0] = v00;  d2[i0 + SS] = v01;
                    d2[i0 + 8] = v10; d2[i0 + SS + 8] = v11;
                }
            }
        }
    }
}

// ---------------------------------------------------------------------------
// Tensor-core flash attention (bf16-split, fp32 softmax/accum).
// CTA: 256 thr / 8 warps, 128 queries; warp w owns rows w*16..+15.
// K-tile 64 keys. Q frags in registers for all 16 k-tiles. P never hits smem:
// score C-fragments are repacked in registers into PV A-fragments.
// Scores = QhKh+QhKl+QlKh; PV = PhVh+PhVl+PlVh  (~1e-5 accuracy).
// ---------------------------------------------------------------------------
#define KSTR 56   // halfword stride for K tiles (48 data + 8 pad)
#define VSTR 72   // halfword stride for V tiles (64 data + 8 pad)

__global__ __launch_bounds__(256) void attn_mma(const float* __restrict__ Q,
                                                const float* __restrict__ K,
                                                const float* __restrict__ V,
                                                float* __restrict__ out) {
    __shared__ __nv_bfloat16 Kh[64 * KSTR], Kl[64 * KSTR];
    __shared__ __nv_bfloat16 Vh[PDIM * VSTR], Vl[PDIM * VSTR];

    const int bh = blockIdx.y;
    const int q0 = blockIdx.x * 128;
    const float* Qb = Q + (size_t)bh * SS * PDIM;
    const float* Kb = K + (size_t)bh * SS * PDIM;
    const float* Vb = V + (size_t)bh * SS * PDIM;   // pd-major: Vb[pd*SS + s]

    const int tid = threadIdx.x;
    const int lane = tid & 31, w = tid >> 5;
    const int g = lane >> 2, tg = lane & 3;
    const float scale = 0.14433756729740643f;  // 1/sqrt(48)

    // Q fragments in registers (scaled, split): rows w*16+g (+8), 3 k-steps
    unsigned qh[3][4], ql[3][4];
#pragma unroll
    for (int ks = 0; ks < 3; ks++)
#pragma unroll
        for (int e = 0; e < 4; e++) {
            const int row = q0 + w * 16 + g + ((e & 1) ? 8 : 0);
            const int col = ks * 16 + 2 * tg + ((e >= 2) ? 8 : 0);
            float2 v = *(const float2*)&Qb[(size_t)row * PDIM + col];
            split2(v.x * scale, v.y * scale, qh[ks][e], ql[ks][e]);
        }

    float m0v = -1e30f, m1v = -1e30f, l0v = 0.0f, l1v = 0.0f;
    float o[6][4];
#pragma unroll
    for (int ns = 0; ns < 6; ns++)
#pragma unroll
        for (int e = 0; e < 4; e++) o[ns][e] = 0.0f;

    for (int kt = 0; kt < 16; kt++) {
        const int k0 = kt * 64;
        __syncthreads();
        // K tile: 64 rows x 48 fp32 -> split bf16 (768 float4, 3/thread)
        for (int i = tid; i < 768; i += 256) {
            const int r = i / 12;
            const int c4 = (i - r * 12) * 4;
            float4 v = *(const float4*)&Kb[(size_t)(k0 + r) * PDIM + c4];
            unsigned h0, l0, h1, l1;
            split2(v.x, v.y, h0, l0);
            split2(v.z, v.w, h1, l1);
            *(uint2*)&Kh[r * KSTR + c4] = make_uint2(h0, h1);
            *(uint2*)&Kl[r * KSTR + c4] = make_uint2(l0, l1);
        }
        // V tile: 48 rows(pd) x 64 fp32 (pd-major) -> split bf16
        for (int i = tid; i < 768; i += 256) {
            const int r = i >> 4;
            const int c4 = (i & 15) * 4;
            float4 v = *(const float4*)&Vb[(size_t)r * SS + k0 + c4];
            unsigned h0, l0, h1, l1;
            split2(v.x, v.y, h0, l0);
            split2(v.z, v.w, h1, l1);
            *(uint2*)&Vh[r * VSTR + c4] = make_uint2(h0, h1);
            *(uint2*)&Vl[r * VSTR + c4] = make_uint2(l0, l1);
        }
        __syncthreads();

        // --- scores: warp m16 x 64 keys = 8 n-steps ---
        float c[8][4];
#pragma unroll
        for (int ns = 0; ns < 8; ns++) {
            c[ns][0] = c[ns][1] = c[ns][2] = c[ns][3] = 0.0f;
            const int nrow = ns * 8 + g;
#pragma unroll
            for (int ks = 0; ks < 3; ks++) {
                unsigned kb_h[2], kb_l[2];
                kb_h[0] = *(const unsigned*)&Kh[nrow * KSTR + ks * 16 + 2 * tg];
                kb_h[1] = *(const unsigned*)&Kh[nrow * KSTR + ks * 16 + 2 * tg + 8];
                kb_l[0] = *(const unsigned*)&Kl[nrow * KSTR + ks * 16 + 2 * tg];
                kb_l[1] = *(const unsigned*)&Kl[nrow * KSTR + ks * 16 + 2 * tg + 8];
                mma16816(c[ns], qh[ks], kb_h);
                mma16816(c[ns], qh[ks], kb_l);
                mma16816(c[ns], ql[ks], kb_h);
            }
        }

        // --- online softmax: row0 = g (elems 0,1), row1 = g+8 (elems 2,3) ---
        float mt0 = -1e30f, mt1 = -1e30f;
#pragma unroll
        for (int ns = 0; ns < 8; ns++) {
            mt0 = fmaxf(mt0, fmaxf(c[ns][0], c[ns][1]));
            mt1 = fmaxf(mt1, fmaxf(c[ns][2], c[ns][3]));
        }
        mt0 = fmaxf(mt0, __shfl_xor_sync(0xffffffffu, mt0, 1));
        mt0 = fmaxf(mt0, __shfl_xor_sync(0xffffffffu, mt0, 2));
        mt1 = fmaxf(mt1, __shfl_xor_sync(0xffffffffu, mt1, 1));
        mt1 = fmaxf(mt1, __shfl_xor_sync(0xffffffffu, mt1, 2));
        const float mn0 = fmaxf(m0v, mt0);
        const float mn1 = fmaxf(m1v, mt1);
        float s0 = 0.0f, s1 = 0.0f;
#pragma unroll
        for (int ns = 0; ns < 8; ns++) {
            c[ns][0] = __expf(c[ns][0] - mn0);
            c[ns][1] = __expf(c[ns][1] - mn0);
            c[ns][2] = __expf(c[ns][2] - mn1);
            c[ns][3] = __expf(c[ns][3] - mn1);
            s0 += c[ns][0] + c[ns][1];
            s1 += c[ns][2] + c[ns][3];
        }
        s0 += __shfl_xor_sync(0xffffffffu, s0, 1);
        s0 += __shfl_xor_sync(0xffffffffu, s0, 2);
        s1 += __shfl_xor_sync(0xffffffffu, s1, 1);
        s1 += __shfl_xor_sync(0xffffffffu, s1, 2);
        const float al0 = __expf(m0v - mn0);
        const float al1 = __expf(m1v - mn1);
        l0v = al0 * l0v + s0;  m0v = mn0;
        l1v = al1 * l1v + s1;  m1v = mn1;

        // --- repack P (hi/lo) into PV A-fragments, in registers ---
        unsigned ph[4][4], pl[4][4];
#pragma unroll
        for (int kp = 0; kp < 4; kp++) {
            split2(c[2 * kp][0],     c[2 * kp][1],     ph[kp][0], pl[kp][0]);
            split2(c[2 * kp][2],     c[2 * kp][3],     ph[kp][1], pl[kp][1]);
            split2(c[2 * kp + 1][0], c[2 * kp + 1][1], ph[kp][2], pl[kp][2]);
            split2(c[2 * kp + 1][2], c[2 * kp + 1][3], ph[kp][3], pl[kp][3]);
        }

        // --- O = alpha*O + P @ V : m16 x 48 pd = 6 n-steps, 4 k-steps ---
#pragma unroll
        for (int ns = 0; ns < 6; ns++) {
            o[ns][0] *= al0; o[ns][1] *= al0;
            o[ns][2] *= al1; o[ns][3] *= al1;
            const int vrow = ns * 8 + g;
#pragma unroll
            for (int kp = 0; kp < 4; kp++) {
                unsigned vb_h[2], vb_l[2];
                vb_h[0] = *(const unsigned*)&Vh[vrow * VSTR + kp * 16 + 2 * tg];
                vb_h[1] = *(const unsigned*)&Vh[vrow * VSTR + kp * 16 + 2 * tg + 8];
                vb_l[0] = *(const unsigned*)&Vl[vrow * VSTR + kp * 16 + 2 * tg];
                vb_l[1] = *(const unsigned*)&Vl[vrow * VSTR + kp * 16 + 2 * tg + 8];
                mma16816(o[ns], ph[kp], vb_h);
                mma16816(o[ns], ph[kp], vb_l);
                mma16816(o[ns], pl[kp], vb_h);
            }
        }
    }

    // epilogue: normalize, write to [b,s,d] concat layout
    const float inv0 = 1.0f / l0v;
    const float inv1 = 1.0f / l1v;
    const int b = bh >> 4;
    const int h = bh & 15;
    const int r0 = q0 + w * 16 + g;
#pragma unroll
    for (int ns = 0; ns < 6; ns++) {
        const int d = h * PDIM + ns * 8 + 2 * tg;
        *(float2*)&out[(size_t)(b * SS + r0) * DD + d] =
            make_float2(o[ns][0] * inv0, o[ns][1] * inv0);
        *(float2*)&out[(size_t)(b * SS + r0 + 8) * DD + d] =
            make_float2(o[ns][2] * inv1, o[ns][3] * inv1);
    }
}

// ---------------------------------------------------------------------------
extern "C" void kernel_launch(void* const* d_in, const int* in_sizes, int n_in,
                              void* d_out, int out_size) {
    const float* X  = (const float*)d_in[0];
    const float* Wq = (const float*)d_in[1];
    const float* bq = (const float*)d_in[2];
    const float* Wk = (const float*)d_in[3];
    const float* bk = (const float*)d_in[4];
    const float* Wv = (const float*)d_in[5];
    const float* bv = (const float*)d_in[6];
    const float* Wo = (const float*)d_in[7];
    const float* bo = (const float*)d_in[8];
    float* out = (float*)d_out;

    __nv_bfloat16 *xhi, *xlo, *chi, *clo, *wthi, *wtlo;
    float *qp, *kp, *vp, *ap;
    cudaGetSymbolAddress((void**)&xhi, g_xhi);
    cudaGetSymbolAddress((void**)&xlo, g_xlo);
    cudaGetSymbolAddress((void**)&chi, g_chi);
    cudaGetSymbolAddress((void**)&clo, g_clo);
    cudaGetSymbolAddress((void**)&wthi, g_wthi);
    cudaGetSymbolAddress((void**)&wtlo, g_wtlo);
    cudaGetSymbolAddress((void**)&qp, g_q);
    cudaGetSymbolAddress((void**)&kp, g_k);
    cudaGetSymbolAddress((void**)&vp, g_v);
    cudaGetSymbolAddress((void**)&ap, g_attn);

    const int n4 = MTOT * DD / 4;
    splitk<<<(n4 + 255) / 256, 256>>>(X, xhi, xlo, n4);
    wsplit<<<dim3(24, 24, 4), dim3(32, 8)>>>(Wq, Wk, Wv, Wo, wthi, wtlo);

    // fused QKV
    mma_gemm<1><<<dim3(36, 64), 256>>>(xhi, xlo, wthi, wtlo, bq, bk, bv, qp, kp, vp);

    attn_mma<<<dim3(SS / 128, BB * HH), 256>>>(qp, kp, vp, ap);

    splitk<<<(n4 + 255) / 256, 256>>>(ap, chi, clo, n4);
    mma_gemm<0><<<dim3(12, 64), 256>>>(chi, clo, wthi + 3 * (size_t)WSZ,
                                       wtlo + 3 * (size_t)WSZ, bo, nullptr, nullptr,
                                       out, nullptr, nullptr);
}

// round 14
// speedup vs baseline: 1.9306x; 1.2706x over previous
#include <cuda_runtime.h>
#include <cuda_bf16.h>

// Problem constants
#define BB   8
#define SS   1024
#define DD   768
#define HH   16
#define PDIM 48
#define MTOT (BB * SS)   // 8192
#define WSZ  (DD * DD)   // 589824
#define QKV  (BB * HH * SS * PDIM)   // 6291456

// ---------------------------------------------------------------------------
// Scratch (device globals: allocation-free)
// ---------------------------------------------------------------------------
__device__ __nv_bfloat16 g_xhi[MTOT * DD], g_xlo[MTOT * DD];   // split(inputs)
__device__ __nv_bfloat16 g_chi[MTOT * DD], g_clo[MTOT * DD];   // split(attn out) [b,s,d]
__device__ __nv_bfloat16 g_wthi[4 * WSZ], g_wtlo[4 * WSZ];     // Wt[n][k] split, slots q,k,v,o
__device__ __nv_bfloat16 g_qh[QKV], g_ql[QKV];   // Q*scale split [b,h,s,pd]
__device__ __nv_bfloat16 g_kh[QKV], g_kl[QKV];   // K split      [b,h,s,pd]
__device__ __nv_bfloat16 g_vh[QKV], g_vl[QKV];   // V split      [b,h,pd,s] (pd-major!)

#define QSCALE 0.14433756729740643f   // 1/sqrt(48)

// ---------------------------------------------------------------------------
// helpers
// ---------------------------------------------------------------------------
__device__ __forceinline__ void split2(float x, float y, unsigned& hi, unsigned& lo) {
    __nv_bfloat16 hx = __float2bfloat16(x), hy = __float2bfloat16(y);
    __nv_bfloat16 lx = __float2bfloat16(x - __bfloat162float(hx));
    __nv_bfloat16 ly = __float2bfloat16(y - __bfloat162float(hy));
    __nv_bfloat162 h2(hx, hy), l2(lx, ly);
    hi = *reinterpret_cast<unsigned*>(&h2);
    lo = *reinterpret_cast<unsigned*>(&l2);
}

__device__ __forceinline__ void split1(float x, __nv_bfloat16& h, __nv_bfloat16& l) {
    h = __float2bfloat16(x);
    l = __float2bfloat16(x - __bfloat162float(h));
}

__device__ __forceinline__ void mma16816(float* c, const unsigned* a, const unsigned* b) {
    asm volatile(
        "mma.sync.aligned.m16n8k16.row.col.f32.bf16.bf16.f32 "
        "{%0,%1,%2,%3},{%4,%5,%6,%7},{%8,%9},{%0,%1,%2,%3};"
        : "+f"(c[0]), "+f"(c[1]), "+f"(c[2]), "+f"(c[3])
        : "r"(a[0]), "r"(a[1]), "r"(a[2]), "r"(a[3]), "r"(b[0]), "r"(b[1]));
}

// ---------------------------------------------------------------------------
// split fp32 -> (hi, lo) bf16, 4 elems/thread (input X only)
// ---------------------------------------------------------------------------
__global__ void splitk(const float* __restrict__ x, __nv_bfloat16* __restrict__ hi,
                       __nv_bfloat16* __restrict__ lo, int n4) {
    int i = blockIdx.x * 256 + threadIdx.x;
    if (i >= n4) return;
    float4 v = ((const float4*)x)[i];
    unsigned h0, l0, h1, l1;
    split2(v.x, v.y, h0, l0);
    split2(v.z, v.w, h1, l1);
    unsigned* ph = (unsigned*)&hi[4 * i];
    unsigned* pl = (unsigned*)&lo[4 * i];
    ph[0] = h0; ph[1] = h1;
    pl[0] = l0; pl[1] = l1;
}

// ---------------------------------------------------------------------------
// Weight transpose + split: Wt[n][k] = W[k][n]; 32x32 tiles, 4 weights by z.
// ---------------------------------------------------------------------------
__global__ void wsplit(const float* __restrict__ w0, const float* __restrict__ w1,
                       const float* __restrict__ w2, const float* __restrict__ w3,
                       __nv_bfloat16* __restrict__ whi, __nv_bfloat16* __restrict__ wlo) {
    __shared__ float tile[32][33];
    const int z = blockIdx.z;
    const float* W = (z == 0) ? w0 : (z == 1) ? w1 : (z == 2) ? w2 : w3;
    const int x0 = blockIdx.x * 32;   // n
    const int y0 = blockIdx.y * 32;   // k
    const int tx = threadIdx.x, ty = threadIdx.y;
    for (int j = ty; j < 32; j += 8)
        tile[j][tx] = W[(size_t)(y0 + j) * DD + x0 + tx];
    __syncthreads();
    for (int j = ty; j < 32; j += 8) {
        float v = tile[tx][j];                 // W[y0+tx][x0+j]
        __nv_bfloat16 h, l;
        split1(v, h, l);
        size_t idx = (size_t)z * WSZ + (size_t)(x0 + j) * DD + y0 + tx;
        whi[idx] = h;
        wlo[idx] = l;
    }
}

// ---------------------------------------------------------------------------
// bf16-split tensor-core GEMM: out[M,N] = A @ W (+bias), K=768.
// CTA 128x64, BK=32, 256 thr (8 warps 4x2), warp 32x32, mma m16n8k16.
// MODE 0: plain row-major fp32 out.
// MODE 1: fused QKV; epilogue splits to bf16 hi/lo in gmem:
//         Q (scaled) / K -> [b,h,s,pd]; V -> [b,h,pd,s].
// ---------------------------------------------------------------------------
template <int MODE>
__global__ __launch_bounds__(256) void mma_gemm(
    const __nv_bfloat16* __restrict__ ahi, const __nv_bfloat16* __restrict__ alo,
    const __nv_bfloat16* __restrict__ wthi, const __nv_bfloat16* __restrict__ wtlo,
    const float* __restrict__ bias0, const float* __restrict__ bias1,
    const float* __restrict__ bias2,
    float* __restrict__ outf,
    __nv_bfloat16* __restrict__ qh, __nv_bfloat16* __restrict__ ql,
    __nv_bfloat16* __restrict__ kh, __nv_bfloat16* __restrict__ kl,
    __nv_bfloat16* __restrict__ vh, __nv_bfloat16* __restrict__ vl) {
    __shared__ __nv_bfloat16 Ah[128 * 40], Al[128 * 40];
    __shared__ __nv_bfloat16 Bh[64 * 40], Bl[64 * 40];

    const int tid = threadIdx.x;
    const int lane = tid & 31, wid = tid >> 5;
    const int wm = wid & 3, wn = wid >> 2;
    const int g = lane >> 2, tg = lane & 3;
    const int m0 = blockIdx.y * 128;

    int w, nloc;
    if (MODE == 1) { w = blockIdx.x / 12; nloc = (blockIdx.x % 12) * 64; }
    else           { w = 0;               nloc = blockIdx.x * 64; }
    const __nv_bfloat16* Wh = wthi + (size_t)w * WSZ;
    const __nv_bfloat16* Wl = wtlo + (size_t)w * WSZ;
    const float* bias = (MODE == 1) ? (w == 0 ? bias0 : (w == 1 ? bias1 : bias2)) : bias0;

    const int ar = tid >> 1, ac = (tid & 1) * 16;     // A: 128 rows x 32 k
    const int br = tid >> 2, bc = (tid & 3) * 8;      // B: 64 rows(n) x 32 k

    float acc[2][4][4];
#pragma unroll
    for (int mt = 0; mt < 2; mt++)
#pragma unroll
        for (int nt = 0; nt < 4; nt++)
#pragma unroll
            for (int e = 0; e < 4; e++) acc[mt][nt][e] = 0.0f;

    for (int k0 = 0; k0 < DD; k0 += 32) {
        const size_t aoff = (size_t)(m0 + ar) * DD + k0 + ac;
        const size_t boff = (size_t)(nloc + br) * DD + k0 + bc;
        uint4 vah0 = *(const uint4*)&ahi[aoff];
        uint4 vah1 = *(const uint4*)&ahi[aoff + 8];
        uint4 val0 = *(const uint4*)&alo[aoff];
        uint4 val1 = *(const uint4*)&alo[aoff + 8];
        uint4 vbh  = *(const uint4*)&Wh[boff];
        uint4 vbl  = *(const uint4*)&Wl[boff];
        __syncthreads();
        {
            uint2* s = (uint2*)&Ah[ar * 40 + ac];
            s[0] = make_uint2(vah0.x, vah0.y); s[1] = make_uint2(vah0.z, vah0.w);
            s[2] = make_uint2(vah1.x, vah1.y); s[3] = make_uint2(vah1.z, vah1.w);
            uint2* t = (uint2*)&Al[ar * 40 + ac];
            t[0] = make_uint2(val0.x, val0.y); t[1] = make_uint2(val0.z, val0.w);
            t[2] = make_uint2(val1.x, val1.y); t[3] = make_uint2(val1.z, val1.w);
            uint2* u = (uint2*)&Bh[br * 40 + bc];
            u[0] = make_uint2(vbh.x, vbh.y);   u[1] = make_uint2(vbh.z, vbh.w);
            uint2* v = (uint2*)&Bl[br * 40 + bc];
            v[0] = make_uint2(vbl.x, vbl.y);   v[1] = make_uint2(vbl.z, vbl.w);
        }
        __syncthreads();

#pragma unroll
        for (int kh2 = 0; kh2 < 32; kh2 += 16) {
            unsigned a_h[2][4], a_l[2][4], b_h[4][2], b_l[4][2];
#pragma unroll
            for (int mt = 0; mt < 2; mt++) {
                const int rb = wm * 32 + mt * 16 + g;
                a_h[mt][0] = *(const unsigned*)&Ah[(rb)     * 40 + kh2 + 2 * tg];
                a_h[mt][1] = *(const unsigned*)&Ah[(rb + 8) * 40 + kh2 + 2 * tg];
                a_h[mt][2] = *(const unsigned*)&Ah[(rb)     * 40 + kh2 + 2 * tg + 8];
                a_h[mt][3] = *(const unsigned*)&Ah[(rb + 8) * 40 + kh2 + 2 * tg + 8];
                a_l[mt][0] = *(const unsigned*)&Al[(rb)     * 40 + kh2 + 2 * tg];
                a_l[mt][1] = *(const unsigned*)&Al[(rb + 8) * 40 + kh2 + 2 * tg];
                a_l[mt][2] = *(const unsigned*)&Al[(rb)     * 40 + kh2 + 2 * tg + 8];
                a_l[mt][3] = *(const unsigned*)&Al[(rb + 8) * 40 + kh2 + 2 * tg + 8];
            }
#pragma unroll
            for (int nt = 0; nt < 4; nt++) {
                const int nb = wn * 32 + nt * 8 + g;
                b_h[nt][0] = *(const unsigned*)&Bh[nb * 40 + kh2 + 2 * tg];
                b_h[nt][1] = *(const unsigned*)&Bh[nb * 40 + kh2 + 2 * tg + 8];
                b_l[nt][0] = *(const unsigned*)&Bl[nb * 40 + kh2 + 2 * tg];
                b_l[nt][1] = *(const unsigned*)&Bl[nb * 40 + kh2 + 2 * tg + 8];
            }
#pragma unroll
            for (int mt = 0; mt < 2; mt++)
#pragma unroll
                for (int nt = 0; nt < 4; nt++) {
                    mma16816(acc[mt][nt], a_h[mt], b_h[nt]);
                    mma16816(acc[mt][nt], a_h[mt], b_l[nt]);
                    mma16816(acc[mt][nt], a_l[mt], b_h[nt]);
                }
        }
    }

    // epilogue
#pragma unroll
    for (int mt = 0; mt < 2; mt++) {
        const int mA = m0 + wm * 32 + mt * 16 + g;
#pragma unroll
        for (int nt = 0; nt < 4; nt++) {
            const int n = nloc + wn * 32 + nt * 8 + tg * 2;
            const float b0v = bias[n], b1v = bias[n + 1];
            const float v00 = acc[mt][nt][0] + b0v;
            const float v01 = acc[mt][nt][1] + b1v;
            const float v10 = acc[mt][nt][2] + b0v;
            const float v11 = acc[mt][nt][3] + b1v;
            if (MODE == 0) {
                *(float2*)&outf[(size_t)mA * DD + n] = make_float2(v00, v01);
                *(float2*)&outf[(size_t)(mA + 8) * DD + n] = make_float2(v10, v11);
            } else {
                const int h = n / PDIM, pd = n - h * PDIM;   // pd even; pd+1 same head
                const int b_ = mA >> 10, s0 = mA & 1023;
                if (w < 2) {                                  // Q (scaled) / K: [b,h,s,pd]
                    const float sc = (w == 0) ? QSCALE : 1.0f;
                    __nv_bfloat16* dh = (w == 0) ? qh : kh;
                    __nv_bfloat16* dl = (w == 0) ? ql : kl;
                    size_t i0 = (((size_t)(b_ * HH + h) << 10) + s0) * PDIM + pd;
                    unsigned h0, l0, h1, l1;
                    split2(v00 * sc, v01 * sc, h0, l0);
                    split2(v10 * sc, v11 * sc, h1, l1);
                    *(unsigned*)&dh[i0] = h0;            *(unsigned*)&dl[i0] = l0;
                    *(unsigned*)&dh[i0 + 8 * PDIM] = h1; *(unsigned*)&dl[i0 + 8 * PDIM] = l1;
                } else {                                      // V: [b,h,pd,s]
                    size_t i0 = (((size_t)(b_ * HH + h) * PDIM + pd) << 10) + s0;
                    __nv_bfloat16 hh, ll;
                    split1(v00, hh, ll); vh[i0] = hh;          vl[i0] = ll;
                    split1(v01, hh, ll); vh[i0 + SS] = hh;     vl[i0 + SS] = ll;
                    split1(v10, hh, ll); vh[i0 + 8] = hh;      vl[i0 + 8] = ll;
                    split1(v11, hh, ll); vh[i0 + SS + 8] = hh; vl[i0 + SS + 8] = ll;
                }
            }
        }
    }
}

// ---------------------------------------------------------------------------
// Tensor-core flash attention. All operands pre-split bf16 in gmem:
// Q (pre-scaled) [b,h,s,pd], K [b,h,s,pd], V [b,h,pd,s].
// CTA: 256 thr / 8 warps, 128 queries; warp w owns rows w*16..+15.
// Load loop = pure bf16 copies (no conversion). 2 CTAs/SM forced.
// Epilogue writes split chi/clo directly (feeds O-projection GEMM).
// ---------------------------------------------------------------------------
#define KSTR 56   // halfword stride for K tiles (48 data + 8 pad)
#define VSTR 72   // halfword stride for V tiles (64 data + 8 pad)

__global__ __launch_bounds__(256, 2) void attn_mma(
    const __nv_bfloat16* __restrict__ Qh, const __nv_bfloat16* __restrict__ Ql,
    const __nv_bfloat16* __restrict__ Kgh, const __nv_bfloat16* __restrict__ Kgl,
    const __nv_bfloat16* __restrict__ Vgh, const __nv_bfloat16* __restrict__ Vgl,
    __nv_bfloat16* __restrict__ chi, __nv_bfloat16* __restrict__ clo) {
    __shared__ __nv_bfloat16 Kh[64 * KSTR], Kl[64 * KSTR];
    __shared__ __nv_bfloat16 Vh[PDIM * VSTR], Vl[PDIM * VSTR];

    const int bh = blockIdx.y;
    const int q0 = blockIdx.x * 128;
    const size_t base = (size_t)bh * SS * PDIM;
    const __nv_bfloat16* Qbh = Qh + base;
    const __nv_bfloat16* Qbl = Ql + base;
    const __nv_bfloat16* Kbh = Kgh + base;
    const __nv_bfloat16* Kbl = Kgl + base;
    const __nv_bfloat16* Vbh = Vgh + base;   // pd-major: [pd*SS + s]
    const __nv_bfloat16* Vbl = Vgl + base;

    const int tid = threadIdx.x;
    const int lane = tid & 31, w = tid >> 5;
    const int g = lane >> 2, tg = lane & 3;

    // Q fragments in registers (pre-scaled, pre-split): rows w*16+g (+8)
    unsigned qh[3][4], ql[3][4];
#pragma unroll
    for (int ks = 0; ks < 3; ks++)
#pragma unroll
        for (int e = 0; e < 4; e++) {
            const int row = q0 + w * 16 + g + ((e & 1) ? 8 : 0);
            const int col = ks * 16 + 2 * tg + ((e >= 2) ? 8 : 0);
            const size_t off = (size_t)row * PDIM + col;
            qh[ks][e] = *(const unsigned*)&Qbh[off];
            ql[ks][e] = *(const unsigned*)&Qbl[off];
        }

    float m0v = -1e30f, m1v = -1e30f, l0v = 0.0f, l1v = 0.0f;
    float o[6][4];
#pragma unroll
    for (int ns = 0; ns < 6; ns++)
#pragma unroll
        for (int e = 0; e < 4; e++) o[ns][e] = 0.0f;

    for (int kt = 0; kt < 16; kt++) {
        const int k0 = kt * 64;
        __syncthreads();
        // K tile: 64 rows x 48 bf16 x2 arrays (uint2 copies, 3/thread each)
        for (int i = tid; i < 768; i += 256) {
            const int r = i / 12;
            const int c4 = (i - r * 12) * 4;
            const size_t goff = (size_t)(k0 + r) * PDIM + c4;
            *(uint2*)&Kh[r * KSTR + c4] = *(const uint2*)&Kbh[goff];
            *(uint2*)&Kl[r * KSTR + c4] = *(const uint2*)&Kbl[goff];
        }
        // V tile: 48 rows(pd) x 64 bf16 x2 arrays
        for (int i = tid; i < 768; i += 256) {
            const int r = i >> 4;
            const int c4 = (i & 15) * 4;
            const size_t goff = (size_t)r * SS + k0 + c4;
            *(uint2*)&Vh[r * VSTR + c4] = *(const uint2*)&Vbh[goff];
            *(uint2*)&Vl[r * VSTR + c4] = *(const uint2*)&Vbl[goff];
        }
        __syncthreads();

        // --- scores: warp m16 x 64 keys = 8 n-steps ---
        float c[8][4];
#pragma unroll
        for (int ns = 0; ns < 8; ns++) {
            c[ns][0] = c[ns][1] = c[ns][2] = c[ns][3] = 0.0f;
            const int nrow = ns * 8 + g;
#pragma unroll
            for (int ks = 0; ks < 3; ks++) {
                unsigned kb_h[2], kb_l[2];
                kb_h[0] = *(const unsigned*)&Kh[nrow * KSTR + ks * 16 + 2 * tg];
                kb_h[1] = *(const unsigned*)&Kh[nrow * KSTR + ks * 16 + 2 * tg + 8];
                kb_l[0] = *(const unsigned*)&Kl[nrow * KSTR + ks * 16 + 2 * tg];
                kb_l[1] = *(const unsigned*)&Kl[nrow * KSTR + ks * 16 + 2 * tg + 8];
                mma16816(c[ns], qh[ks], kb_h);
                mma16816(c[ns], qh[ks], kb_l);
                mma16816(c[ns], ql[ks], kb_h);
            }
        }

        // --- online softmax: row0 = g (elems 0,1), row1 = g+8 (elems 2,3) ---
        float mt0 = -1e30f, mt1 = -1e30f;
#pragma unroll
        for (int ns = 0; ns < 8; ns++) {
            mt0 = fmaxf(mt0, fmaxf(c[ns][0], c[ns][1]));
            mt1 = fmaxf(mt1, fmaxf(c[ns][2], c[ns][3]));
        }
        mt0 = fmaxf(mt0, __shfl_xor_sync(0xffffffffu, mt0, 1));
        mt0 = fmaxf(mt0, __shfl_xor_sync(0xffffffffu, mt0, 2));
        mt1 = fmaxf(mt1, __shfl_xor_sync(0xffffffffu, mt1, 1));
        mt1 = fmaxf(mt1, __shfl_xor_sync(0xffffffffu, mt1, 2));
        const float mn0 = fmaxf(m0v, mt0);
        const float mn1 = fmaxf(m1v, mt1);
        float s0 = 0.0f, s1 = 0.0f;
#pragma unroll
        for (int ns = 0; ns < 8; ns++) {
            c[ns][0] = __expf(c[ns][0] - mn0);
            c[ns][1] = __expf(c[ns][1] - mn0);
            c[ns][2] = __expf(c[ns][2] - mn1);
            c[ns][3] = __expf(c[ns][3] - mn1);
            s0 += c[ns][0] + c[ns][1];
            s1 += c[ns][2] + c[ns][3];
        }
        s0 += __shfl_xor_sync(0xffffffffu, s0, 1);
        s0 += __shfl_xor_sync(0xffffffffu, s0, 2);
        s1 += __shfl_xor_sync(0xffffffffu, s1, 1);
        s1 += __shfl_xor_sync(0xffffffffu, s1, 2);
        const float al0 = __expf(m0v - mn0);
        const float al1 = __expf(m1v - mn1);
        l0v = al0 * l0v + s0;  m0v = mn0;
        l1v = al1 * l1v + s1;  m1v = mn1;

        // --- repack P (hi/lo) into PV A-fragments, in registers ---
        unsigned ph[4][4], pl[4][4];
#pragma unroll
        for (int kp = 0; kp < 4; kp++) {
            split2(c[2 * kp][0],     c[2 * kp][1],     ph[kp][0], pl[kp][0]);
            split2(c[2 * kp][2],     c[2 * kp][3],     ph[kp][1], pl[kp][1]);
            split2(c[2 * kp + 1][0], c[2 * kp + 1][1], ph[kp][2], pl[kp][2]);
            split2(c[2 * kp + 1][2], c[2 * kp + 1][3], ph[kp][3], pl[kp][3]);
        }

        // --- O = alpha*O + P @ V : m16 x 48 pd = 6 n-steps, 4 k-steps ---
#pragma unroll
        for (int ns = 0; ns < 6; ns++) {
            o[ns][0] *= al0; o[ns][1] *= al0;
            o[ns][2] *= al1; o[ns][3] *= al1;
            const int vrow = ns * 8 + g;
#pragma unroll
            for (int kp = 0; kp < 4; kp++) {
                unsigned vb_h[2], vb_l[2];
                vb_h[0] = *(const unsigned*)&Vh[vrow * VSTR + kp * 16 + 2 * tg];
                vb_h[1] = *(const unsigned*)&Vh[vrow * VSTR + kp * 16 + 2 * tg + 8];
                vb_l[0] = *(const unsigned*)&Vl[vrow * VSTR + kp * 16 + 2 * tg];
                vb_l[1] = *(const unsigned*)&Vl[vrow * VSTR + kp * 16 + 2 * tg + 8];
                mma16816(o[ns], ph[kp], vb_h);
                mma16816(o[ns], ph[kp], vb_l);
                mma16816(o[ns], pl[kp], vb_h);
            }
        }
    }

    // epilogue: normalize, split, write chi/clo [b,s,d]
    const float inv0 = 1.0f / l0v;
    const float inv1 = 1.0f / l1v;
    const int b = bh >> 4;
    const int h = bh & 15;
    const int r0 = q0 + w * 16 + g;
#pragma unroll
    for (int ns = 0; ns < 6; ns++) {
        const int d = h * PDIM + ns * 8 + 2 * tg;
        const size_t i0 = (size_t)(b * SS + r0) * DD + d;
        const size_t i1 = (size_t)(b * SS + r0 + 8) * DD + d;
        unsigned h0, l0, h1, l1;
        split2(o[ns][0] * inv0, o[ns][1] * inv0, h0, l0);
        split2(o[ns][2] * inv1, o[ns][3] * inv1, h1, l1);
        *(unsigned*)&chi[i0] = h0; *(unsigned*)&clo[i0] = l0;
        *(unsigned*)&chi[i1] = h1; *(unsigned*)&clo[i1] = l1;
    }
}

// ---------------------------------------------------------------------------
extern "C" void kernel_launch(void* const* d_in, const int* in_sizes, int n_in,
                              void* d_out, int out_size) {
    const float* X  = (const float*)d_in[0];
    const float* Wq = (const float*)d_in[1];
    const float* bq = (const float*)d_in[2];
    const float* Wk = (const float*)d_in[3];
    const float* bk = (const float*)d_in[4];
    const float* Wv = (const float*)d_in[5];
    const float* bv = (const float*)d_in[6];
    const float* Wo = (const float*)d_in[7];
    const float* bo = (const float*)d_in[8];
    float* out = (float*)d_out;

    __nv_bfloat16 *xhi, *xlo, *chi, *clo, *wthi, *wtlo;
    __nv_bfloat16 *qh, *ql, *kh, *kl, *vh, *vl;
    cudaGetSymbolAddress((void**)&xhi, g_xhi);
    cudaGetSymbolAddress((void**)&xlo, g_xlo);
    cudaGetSymbolAddress((void**)&chi, g_chi);
    cudaGetSymbolAddress((void**)&clo, g_clo);
    cudaGetSymbolAddress((void**)&wthi, g_wthi);
    cudaGetSymbolAddress((void**)&wtlo, g_wtlo);
    cudaGetSymbolAddress((void**)&qh, g_qh);
    cudaGetSymbolAddress((void**)&ql, g_ql);
    cudaGetSymbolAddress((void**)&kh, g_kh);
    cudaGetSymbolAddress((void**)&kl, g_kl);
    cudaGetSymbolAddress((void**)&vh, g_vh);
    cudaGetSymbolAddress((void**)&vl, g_vl);

    const int n4 = MTOT * DD / 4;
    splitk<<<(n4 + 255) / 256, 256>>>(X, xhi, xlo, n4);
    wsplit<<<dim3(24, 24, 4), dim3(32, 8)>>>(Wq, Wk, Wv, Wo, wthi, wtlo);

    // fused QKV: epilogue writes pre-split bf16 Q/K/V
    mma_gemm<1><<<dim3(36, 64), 256>>>(xhi, xlo, wthi, wtlo, bq, bk, bv,
                                       nullptr, qh, ql, kh, kl, vh, vl);

    attn_mma<<<dim3(SS / 128, BB * HH), 256>>>(qh, ql, kh, kl, vh, vl, chi, clo);

    mma_gemm<0><<<dim3(12, 64), 256>>>(chi, clo, wthi + 3 * (size_t)WSZ,
                                       wtlo + 3 * (size_t)WSZ, bo, nullptr, nullptr,
                                       out, nullptr, nullptr, nullptr, nullptr,
                                       nullptr, nullptr);
}